// round 7
// baseline (speedup 1.0000x reference)
#include <cuda_runtime.h>
#include <cuda_fp16.h>
#include <cstdint>

#define NHID     128
#define KDIM     256
#define TILE_M   128
#define THREADS  512
#define GRID     152
#define NCHUNKS  4       // 64-wide k chunks

// ---------------- smem layout (bytes) ----------------
// B frag fp16 : [nt 16][gks16 16][lane 32][8B]   = 65536
// A frag fp16 : 2 x [mt 8][ks16 4][lane 32][16B] = 2 x 16384
#define OFF_BFRAG  0
#define OFF_AF0    65536
#define OFF_AF1    81920
#define OFF_SXI    98304
#define OFF_SYI    98816
#define OFF_SRED   99328
#define SMEM_TOTAL 101376

// ---------------- PTX helpers ----------------
__device__ __forceinline__ uint32_t smem_u32(const void* p) {
    uint32_t a;
    asm("{ .reg .u64 t; cvta.to.shared.u64 t, %1; cvt.u32.u64 %0, t; }" : "=r"(a) : "l"(p));
    return a;
}
__device__ __forceinline__ uint32_t f2h2(float lo, float hi) {   // {lo, hi} packed
    uint32_t v;
    asm("cvt.rn.f16x2.f32 %0, %1, %2;" : "=r"(v) : "f"(hi), "f"(lo));
    return v;
}
__device__ __forceinline__ void sts32(uint32_t addr, uint32_t v) {
    asm volatile("st.shared.b32 [%0], %1;" :: "r"(addr), "r"(v) : "memory");
}
__device__ __forceinline__ void mma_f16(float& c0, float& c1, float& c2, float& c3,
                                        uint32_t a0, uint32_t a1, uint32_t a2, uint32_t a3,
                                        uint32_t b0, uint32_t b1) {
    asm volatile("mma.sync.aligned.m16n8k16.row.col.f32.f16.f16.f32 "
                 "{%0,%1,%2,%3}, {%4,%5,%6,%7}, {%8,%9}, {%0,%1,%2,%3};"
                 : "+f"(c0), "+f"(c1), "+f"(c2), "+f"(c3)
                 : "r"(a0), "r"(a1), "r"(a2), "r"(a3), "r"(b0), "r"(b1));
}

// ---------------- index width autodetect ----------------
__device__ int g_idx_is64;
__global__ void detect_idx_width(const long long* xi, int n_nodes) {
    int is64 = 1;
    for (int i = 0; i < 16; ++i) {
        long long v = xi[i];
        if (v < 0 || v >= (long long)n_nodes) { is64 = 0; break; }
    }
    g_idx_is64 = is64;
}

// ---------------- main kernel ----------------
extern __shared__ char smem[];

__global__ void __launch_bounds__(THREADS, 1)
mlp_decoder_h3(const float* __restrict__ inputs,
               const void*  __restrict__ x_idx_raw,
               const void*  __restrict__ y_idx_raw,
               const float* __restrict__ W1,
               const float* __restrict__ bias1,
               const float* __restrict__ W2,
               const float* __restrict__ bias2,
               float* __restrict__ out,
               int n_edges)
{
    const int tid  = threadIdx.x;
    const int wid  = tid >> 5;
    const int lane = tid & 31;
    const int g    = lane >> 2;
    const int t    = lane & 3;
    const int mw   = wid >> 2;      // m-group (0..3): mtiles mw*2..+1
    const int nw   = wid & 3;       // n-group (0..3): ntiles nw*4..+3
    const uint32_t sbase = smem_u32(smem);

    int* sxi = (int*)(smem + OFF_SXI);
    int* syi = (int*)(smem + OFF_SYI);
    float* sred = (float*)(smem + OFF_SRED);

    const int idx64 = g_idx_is64;
    const long long* xi64 = (const long long*)x_idx_raw;
    const long long* yi64 = (const long long*)y_idx_raw;
    const int*       xi32 = (const int*)x_idx_raw;
    const int*       yi32 = (const int*)y_idx_raw;

    // ---- one-time: W1 -> fp16 B fragment table ----
    // slot i: nt=i>>9, gks16=(i>>5)&15, l=i&31 (gg=l>>2, tt=l&3)
    // b0={W1[k0][n],W1[k0+1][n]}, b1={W1[k0+8][n],W1[k0+9][n]}, k0=gks16*16+2tt
    for (int i = tid; i < 16 * 16 * 32; i += THREADS) {
        int nt = i >> 9, ks = (i >> 5) & 15, l = i & 31;
        int gg = l >> 2, tt = l & 3;
        int k0 = ks * 16 + 2 * tt, n = nt * 8 + gg;
        uint32_t b0 = f2h2(W1[k0 * NHID + n],       W1[(k0 + 1) * NHID + n]);
        uint32_t b1 = f2h2(W1[(k0 + 8) * NHID + n], W1[(k0 + 9) * NHID + n]);
        sts32(sbase + OFF_BFRAG + (uint32_t)i * 8,     b0);
        sts32(sbase + OFF_BFRAG + (uint32_t)i * 8 + 4, b1);
    }

    // ---- per-thread epilogue constants (cols t*2, t*2+1 of each nt) ----
    float b1r[8], w2r[8];
    #pragma unroll
    for (int nt = 0; nt < 4; ++nt) {
        int col = (nw * 4 + nt) * 8 + t * 2;
        b1r[nt * 2]     = bias1[col];
        b1r[nt * 2 + 1] = bias1[col + 1];
        w2r[nt * 2]     = W2[col];
        w2r[nt * 2 + 1] = W2[col + 1];
    }
    const float b2 = bias2[0];

    __syncthreads();

    // gather geometry: thread covers edges ge+32r (r=0..3), float4 slot gq
    const int ge = tid >> 4;        // 0..31
    const int gq = tid & 15;        // float4 index within 64-float chunk

    const int ntiles = (n_edges + TILE_M - 1) / TILE_M;
    for (int tile = blockIdx.x; tile < ntiles; tile += GRID) {
        const int ebase = tile * TILE_M;

        for (int i = tid; i < TILE_M; i += THREADS) {
            int e = ebase + i; if (e >= n_edges) e = n_edges - 1;
            sxi[i] = idx64 ? (int)xi64[e] : xi32[e];
            syi[i] = idx64 ? (int)yi64[e] : yi32[e];
        }
        __syncthreads();

        float4 pf[4];
        auto prefetch = [&](int c) {
            const int* idxarr = (c < 2) ? sxi : syi;
            const int kbase = (c & 1) * 64;
            #pragma unroll
            for (int r = 0; r < 4; ++r) {
                int e = ge + r * 32;
                pf[r] = *(const float4*)(inputs + (size_t)idxarr[e] * NHID + kbase + gq * 4);
            }
        };
        auto sts_chunk = [&](int c) {
            const uint32_t abuf = sbase + ((c & 1) ? OFF_AF1 : OFF_AF0);
            const int ks16 = gq >> 2;          // 0..3
            const int kk0  = (gq & 3) * 4;     // 0,4,8,12
            const int t1   = (kk0 & 7) >> 1;   // 0 or 2
            const int rhi  = (kk0 >= 8) ? 2 : 0;
            #pragma unroll
            for (int r = 0; r < 4; ++r) {
                int e = ge + r * 32;
                int mt = e >> 4, rr = e & 15;
                int gg = rr & 7, hi = rr >> 3;
                uint32_t addr = abuf + (uint32_t)(((mt * 4 + ks16) * 32 + (gg * 4 + t1)) * 16
                                                  + (hi + rhi) * 4);
                sts32(addr,      f2h2(pf[r].x, pf[r].y));
                sts32(addr + 16, f2h2(pf[r].z, pf[r].w));
            }
        };

        prefetch(0);
        sts_chunk(0);
        __syncthreads();

        float acc[2][4][4];
        #pragma unroll
        for (int mt = 0; mt < 2; ++mt)
            #pragma unroll
            for (int nt = 0; nt < 4; ++nt)
                #pragma unroll
                for (int r = 0; r < 4; ++r) acc[mt][nt][r] = 0.0f;

        for (int c = 0; c < NCHUNKS; ++c) {
            if (c < NCHUNKS - 1) prefetch(c + 1);   // LDG in flight during MMA

            const uint32_t aoff = (c & 1) ? OFF_AF1 : OFF_AF0;
            #pragma unroll
            for (int ks = 0; ks < 4; ++ks) {
                const int gks = c * 4 + ks;
                uint2 bf[4];
                #pragma unroll
                for (int nt = 0; nt < 4; ++nt)
                    bf[nt] = *(const uint2*)(smem + OFF_BFRAG +
                              (size_t)(((nw * 4 + nt) * 16 + gks) * 32 + lane) * 8);
                #pragma unroll
                for (int mt = 0; mt < 2; ++mt) {
                    const int mta = mw * 2 + mt;
                    uint4 af = *(const uint4*)(smem + aoff +
                              (size_t)(((mta * 4 + ks) * 32 + lane)) * 16);
                    #pragma unroll
                    for (int nt = 0; nt < 4; ++nt)
                        mma_f16(acc[mt][nt][0], acc[mt][nt][1],
                                acc[mt][nt][2], acc[mt][nt][3],
                                af.x, af.y, af.z, af.w, bf[nt].x, bf[nt].y);
                }
            }

            if (c < NCHUNKS - 1) {
                sts_chunk(c + 1);
                __syncthreads();
            }
        }

        // ---- epilogue: relu + W2 dot, reduce t-lanes then n-groups ----
        #pragma unroll
        for (int mt = 0; mt < 2; ++mt) {
            #pragma unroll
            for (int h = 0; h < 2; ++h) {
                float s = 0.0f;
                #pragma unroll
                for (int nt = 0; nt < 4; ++nt) {
                    float ca = acc[mt][nt][h * 2];
                    float cb = acc[mt][nt][h * 2 + 1];
                    s += fmaxf(ca + b1r[nt * 2],     0.0f) * w2r[nt * 2];
                    s += fmaxf(cb + b1r[nt * 2 + 1], 0.0f) * w2r[nt * 2 + 1];
                }
                s += __shfl_xor_sync(0xffffffffu, s, 1);
                s += __shfl_xor_sync(0xffffffffu, s, 2);
                if (t == 0) {
                    int row = (mw * 2 + mt) * 16 + g + h * 8;
                    sred[row * 4 + nw] = s;
                }
            }
        }
        __syncthreads();

        if (tid < TILE_M) {
            float4 v = *(const float4*)(sred + tid * 4);
            float sum = (v.x + v.y) + (v.z + v.w) + b2;
            int e = ebase + tid;
            if (e < n_edges)
                out[e] = 1.0f / (1.0f + __expf(-sum));
        }
        __syncthreads();
    }
}

// ---------------- launch ----------------
extern "C" void kernel_launch(void* const* d_in, const int* in_sizes, int n_in,
                              void* d_out, int out_size)
{
    const float* inputs = (const float*)d_in[0];
    const void*  x_idx  = d_in[1];
    const void*  y_idx  = d_in[2];
    const float* W1     = (const float*)d_in[3];
    const float* bias1  = (const float*)d_in[4];
    const float* W2     = (const float*)d_in[5];
    const float* bias2  = (const float*)d_in[6];
    float* out = (float*)d_out;

    const int n_edges = in_sizes[1];
    const int n_nodes = in_sizes[0] / NHID;

    detect_idx_width<<<1, 1>>>((const long long*)x_idx, n_nodes);

    cudaFuncSetAttribute(mlp_decoder_h3,
                         cudaFuncAttributeMaxDynamicSharedMemorySize, SMEM_TOTAL);
    mlp_decoder_h3<<<GRID, THREADS, SMEM_TOTAL>>>(
        inputs, x_idx, y_idx, W1, bias1, W2, bias2, out, n_edges);
}

// round 8
// speedup vs baseline: 1.2096x; 1.2096x over previous
#include <cuda_runtime.h>
#include <cuda_fp16.h>
#include <cstdint>

#define NHID     128
#define KDIM     256
#define TILE_M   128
#define THREADS  256
#define NCTAS    2
#define GRID     (152 * NCTAS)
#define NCHUNKS  4       // 64-wide k chunks

// ---------------- smem layout (bytes, per CTA) ----------------
// B frag fp16 : [nt 16][gks16 16][lane 32][8B]   = 65536
// A frag fp16 : 2 x [mt 8][ks16 4][lane 32][16B] = 2 x 16384
#define OFF_BFRAG  0
#define OFF_AF0    65536
#define OFF_AF1    81920
#define OFF_SXI    98304
#define OFF_SYI    98816
#define OFF_SB1    99328
#define OFF_SW2    99840
#define OFF_SRED   100352
#define SMEM_TOTAL 102400

// ---------------- PTX helpers ----------------
__device__ __forceinline__ uint32_t smem_u32(const void* p) {
    uint32_t a;
    asm("{ .reg .u64 t; cvta.to.shared.u64 t, %1; cvt.u32.u64 %0, t; }" : "=r"(a) : "l"(p));
    return a;
}
__device__ __forceinline__ uint32_t f2h2(float lo, float hi) {   // {lo, hi} packed
    uint32_t v;
    asm("cvt.rn.f16x2.f32 %0, %1, %2;" : "=r"(v) : "f"(hi), "f"(lo));
    return v;
}
__device__ __forceinline__ void sts32(uint32_t addr, uint32_t v) {
    asm volatile("st.shared.b32 [%0], %1;" :: "r"(addr), "r"(v) : "memory");
}
__device__ __forceinline__ void mma_f16(float& c0, float& c1, float& c2, float& c3,
                                        uint32_t a0, uint32_t a1, uint32_t a2, uint32_t a3,
                                        uint32_t b0, uint32_t b1) {
    asm volatile("mma.sync.aligned.m16n8k16.row.col.f32.f16.f16.f32 "
                 "{%0,%1,%2,%3}, {%4,%5,%6,%7}, {%8,%9}, {%0,%1,%2,%3};"
                 : "+f"(c0), "+f"(c1), "+f"(c2), "+f"(c3)
                 : "r"(a0), "r"(a1), "r"(a2), "r"(a3), "r"(b0), "r"(b1));
}

// ---------------- index width autodetect ----------------
__device__ int g_idx_is64;
__global__ void detect_idx_width(const long long* xi, int n_nodes) {
    int is64 = 1;
    for (int i = 0; i < 16; ++i) {
        long long v = xi[i];
        if (v < 0 || v >= (long long)n_nodes) { is64 = 0; break; }
    }
    g_idx_is64 = is64;
}

// ---------------- main kernel ----------------
extern __shared__ char smem[];

__global__ void __launch_bounds__(THREADS, NCTAS)
mlp_decoder_h4(const float* __restrict__ inputs,
               const void*  __restrict__ x_idx_raw,
               const void*  __restrict__ y_idx_raw,
               const float* __restrict__ W1,
               const float* __restrict__ bias1,
               const float* __restrict__ W2,
               const float* __restrict__ bias2,
               float* __restrict__ out,
               int n_edges)
{
    const int tid  = threadIdx.x;
    const int wid  = tid >> 5;
    const int lane = tid & 31;
    const int g    = lane >> 2;
    const int t    = lane & 3;
    const int mw   = wid >> 2;      // m-group (0..1): mtiles mw*4..+3
    const int nw   = wid & 3;       // n-group (0..3): ntiles nw*4..+3
    const uint32_t sbase = smem_u32(smem);

    int* sxi = (int*)(smem + OFF_SXI);
    int* syi = (int*)(smem + OFF_SYI);
    float* sb1  = (float*)(smem + OFF_SB1);
    float* sw2  = (float*)(smem + OFF_SW2);
    float* sred = (float*)(smem + OFF_SRED);

    const int idx64 = g_idx_is64;
    const long long* xi64 = (const long long*)x_idx_raw;
    const long long* yi64 = (const long long*)y_idx_raw;
    const int*       xi32 = (const int*)x_idx_raw;
    const int*       yi32 = (const int*)y_idx_raw;

    // ---- one-time: W1 -> fp16 B fragment table ----
    for (int i = tid; i < 16 * 16 * 32; i += THREADS) {
        int nt = i >> 9, ks = (i >> 5) & 15, l = i & 31;
        int gg = l >> 2, tt = l & 3;
        int k0 = ks * 16 + 2 * tt, n = nt * 8 + gg;
        uint32_t b0 = f2h2(W1[k0 * NHID + n],       W1[(k0 + 1) * NHID + n]);
        uint32_t b1 = f2h2(W1[(k0 + 8) * NHID + n], W1[(k0 + 9) * NHID + n]);
        sts32(sbase + OFF_BFRAG + (uint32_t)i * 8,     b0);
        sts32(sbase + OFF_BFRAG + (uint32_t)i * 8 + 4, b1);
    }
    for (int i = tid; i < NHID; i += THREADS) { sb1[i] = bias1[i]; sw2[i] = W2[i]; }
    const float b2 = bias2[0];

    __syncthreads();

    // gather geometry: thread covers edges ge+16r (r=0..7), float4 slot gq
    const int ge = tid >> 4;        // 0..15
    const int gq = tid & 15;        // float4 index within 64-float chunk

    // fragment-scatter constants (from gq), fixed per thread
    const int ks16 = gq >> 2;          // 0..3
    const int kk0  = (gq & 3) * 4;     // 0,4,8,12
    const int t1   = (kk0 & 7) >> 1;   // 0 or 2
    const int rhi  = (kk0 >= 8) ? 2 : 0;

    const int ntiles = (n_edges + TILE_M - 1) / TILE_M;
    for (int tile = blockIdx.x; tile < ntiles; tile += GRID) {
        const int ebase = tile * TILE_M;

        for (int i = tid; i < TILE_M; i += THREADS) {
            int e = ebase + i; if (e >= n_edges) e = n_edges - 1;
            sxi[i] = idx64 ? (int)xi64[e] : xi32[e];
            syi[i] = idx64 ? (int)yi64[e] : yi32[e];
        }
        __syncthreads();

        float4 pf[4];
        // prefetch half h (edges ge + (4h+r)*16, r=0..3) of chunk c
        auto prefetch = [&](int c, int h) {
            const int* idxarr = (c < 2) ? sxi : syi;
            const int kbase = (c & 1) * 64;
            #pragma unroll
            for (int r = 0; r < 4; ++r) {
                int e = ge + (h * 4 + r) * 16;
                pf[r] = *(const float4*)(inputs + (size_t)idxarr[e] * NHID + kbase + gq * 4);
            }
        };
        // convert + scatter pf (half h) into fp16 A fragment buffer of chunk c
        auto sts_half = [&](int c, int h) {
            const uint32_t abuf = sbase + ((c & 1) ? OFF_AF1 : OFF_AF0);
            #pragma unroll
            for (int r = 0; r < 4; ++r) {
                int e = ge + (h * 4 + r) * 16;
                int mt = e >> 4, rr = e & 15;
                int gg = rr & 7, hi = rr >> 3;
                uint32_t addr = abuf + (uint32_t)(((mt * 4 + ks16) * 32 + (gg * 4 + t1)) * 16
                                                  + (hi + rhi) * 4);
                sts32(addr,      f2h2(pf[r].x, pf[r].y));
                sts32(addr + 16, f2h2(pf[r].z, pf[r].w));
            }
        };

        prefetch(0, 0); sts_half(0, 0);
        prefetch(0, 1); sts_half(0, 1);
        __syncthreads();

        float acc[4][4][4];
        #pragma unroll
        for (int mt = 0; mt < 4; ++mt)
            #pragma unroll
            for (int nt = 0; nt < 4; ++nt)
                #pragma unroll
                for (int r = 0; r < 4; ++r) acc[mt][nt][r] = 0.0f;

        for (int c = 0; c < NCHUNKS; ++c) {
            const uint32_t aoff = (c & 1) ? OFF_AF1 : OFF_AF0;

            if (c < NCHUNKS - 1) prefetch(c + 1, 0);

            #pragma unroll
            for (int ks = 0; ks < 4; ++ks) {
                if (ks == 2 && c < NCHUNKS - 1) {   // mid-loop: commit half0, fetch half1
                    sts_half(c + 1, 0);
                    prefetch(c + 1, 1);
                }
                const int gks = c * 4 + ks;
                uint2 bf[4];
                #pragma unroll
                for (int nt = 0; nt < 4; ++nt)
                    bf[nt] = *(const uint2*)(smem + OFF_BFRAG +
                              (size_t)(((nw * 4 + nt) * 16 + gks) * 32 + lane) * 8);
                #pragma unroll
                for (int mt = 0; mt < 4; ++mt) {
                    uint4 af = *(const uint4*)(smem + aoff +
                              (size_t)(((mw * 4 + mt) * 4 + ks) * 32 + lane) * 16);
                    #pragma unroll
                    for (int nt = 0; nt < 4; ++nt)
                        mma_f16(acc[mt][nt][0], acc[mt][nt][1],
                                acc[mt][nt][2], acc[mt][nt][3],
                                af.x, af.y, af.z, af.w, bf[nt].x, bf[nt].y);
                }
            }

            if (c < NCHUNKS - 1) {
                sts_half(c + 1, 1);
                __syncthreads();
            }
        }

        // ---- epilogue: relu + W2 dot (consts from smem), reduce lanes/groups ----
        #pragma unroll
        for (int mt = 0; mt < 4; ++mt) {
            #pragma unroll
            for (int h = 0; h < 2; ++h) {
                float s = 0.0f;
                #pragma unroll
                for (int nt = 0; nt < 4; ++nt) {
                    int col = (nw * 4 + nt) * 8 + t * 2;
                    float ca = acc[mt][nt][h * 2];
                    float cb = acc[mt][nt][h * 2 + 1];
                    s += fmaxf(ca + sb1[col],     0.0f) * sw2[col];
                    s += fmaxf(cb + sb1[col + 1], 0.0f) * sw2[col + 1];
                }
                s += __shfl_xor_sync(0xffffffffu, s, 1);
                s += __shfl_xor_sync(0xffffffffu, s, 2);
                if (t == 0) {
                    int row = (mw * 4 + mt) * 16 + g + h * 8;
                    sred[row * 4 + nw] = s;
                }
            }
        }
        __syncthreads();

        if (tid < TILE_M) {
            float4 v = *(const float4*)(sred + tid * 4);
            float sum = (v.x + v.y) + (v.z + v.w) + b2;
            int e = ebase + tid;
            if (e < n_edges)
                out[e] = 1.0f / (1.0f + __expf(-sum));
        }
        __syncthreads();
    }
}

// ---------------- launch ----------------
extern "C" void kernel_launch(void* const* d_in, const int* in_sizes, int n_in,
                              void* d_out, int out_size)
{
    const float* inputs = (const float*)d_in[0];
    const void*  x_idx  = d_in[1];
    const void*  y_idx  = d_in[2];
    const float* W1     = (const float*)d_in[3];
    const float* bias1  = (const float*)d_in[4];
    const float* W2     = (const float*)d_in[5];
    const float* bias2  = (const float*)d_in[6];
    float* out = (float*)d_out;

    const int n_edges = in_sizes[1];
    const int n_nodes = in_sizes[0] / NHID;

    detect_idx_width<<<1, 1>>>((const long long*)x_idx, n_nodes);

    cudaFuncSetAttribute(mlp_decoder_h4,
                         cudaFuncAttributeMaxDynamicSharedMemorySize, SMEM_TOTAL);
    mlp_decoder_h4<<<GRID, THREADS, SMEM_TOTAL>>>(
        inputs, x_idx, y_idx, W1, bias1, W2, bias2, out, n_edges);
}

// round 9
// speedup vs baseline: 1.3932x; 1.1518x over previous
#include <cuda_runtime.h>
#include <cuda_fp16.h>
#include <cstdint>

#define NHID     128
#define KDIM     256
#define TILE_M   128
#define THREADS  256
#define NCTAS    2
#define GRID     (152 * NCTAS)
#define NCHUNKS  4       // 64-wide k chunks
#define AROW     144     // bytes per staged edge row (64 fp16 = 128B + 16B pad)

// ---------------- smem layout (bytes, per CTA) ----------------
// B frag fp16 : [nt 16][gks16 16][lane 32][8B]  = 65536
// A stage fp16: 2 x [edge 128][AROW]            = 2 x 18432
#define OFF_BFRAG  0
#define OFF_AF0    65536
#define OFF_AF1    83968
#define OFF_SXI    102400
#define OFF_SYI    102912
#define OFF_SB1    103424
#define OFF_SW2    103936
#define OFF_SRED   104448
#define SMEM_TOTAL 106496

// ---------------- PTX helpers ----------------
__device__ __forceinline__ uint32_t smem_u32(const void* p) {
    uint32_t a;
    asm("{ .reg .u64 t; cvta.to.shared.u64 t, %1; cvt.u32.u64 %0, t; }" : "=r"(a) : "l"(p));
    return a;
}
__device__ __forceinline__ uint32_t f2h2(float lo, float hi) {   // {lo, hi} packed
    uint32_t v;
    asm("cvt.rn.f16x2.f32 %0, %1, %2;" : "=r"(v) : "f"(hi), "f"(lo));
    return v;
}
__device__ __forceinline__ void sts64(uint32_t addr, uint32_t v0, uint32_t v1) {
    asm volatile("st.shared.v2.b32 [%0], {%1, %2};" :: "r"(addr), "r"(v0), "r"(v1) : "memory");
}
__device__ __forceinline__ void ldsm4(uint32_t& r0, uint32_t& r1, uint32_t& r2, uint32_t& r3,
                                      uint32_t addr) {
    asm volatile("ldmatrix.sync.aligned.m8n8.x4.shared.b16 {%0,%1,%2,%3}, [%4];"
                 : "=r"(r0), "=r"(r1), "=r"(r2), "=r"(r3) : "r"(addr));
}
__device__ __forceinline__ void mma_f16(float& c0, float& c1, float& c2, float& c3,
                                        uint32_t a0, uint32_t a1, uint32_t a2, uint32_t a3,
                                        uint32_t b0, uint32_t b1) {
    asm volatile("mma.sync.aligned.m16n8k16.row.col.f32.f16.f16.f32 "
                 "{%0,%1,%2,%3}, {%4,%5,%6,%7}, {%8,%9}, {%0,%1,%2,%3};"
                 : "+f"(c0), "+f"(c1), "+f"(c2), "+f"(c3)
                 : "r"(a0), "r"(a1), "r"(a2), "r"(a3), "r"(b0), "r"(b1));
}

// ---------------- index width autodetect ----------------
__device__ int g_idx_is64;
__global__ void detect_idx_width(const long long* xi, int n_nodes) {
    int is64 = 1;
    for (int i = 0; i < 16; ++i) {
        long long v = xi[i];
        if (v < 0 || v >= (long long)n_nodes) { is64 = 0; break; }
    }
    g_idx_is64 = is64;
}

// ---------------- main kernel ----------------
extern __shared__ char smem[];

__global__ void __launch_bounds__(THREADS, NCTAS)
mlp_decoder_h5(const float* __restrict__ inputs,
               const void*  __restrict__ x_idx_raw,
               const void*  __restrict__ y_idx_raw,
               const float* __restrict__ W1,
               const float* __restrict__ bias1,
               const float* __restrict__ W2,
               const float* __restrict__ bias2,
               float* __restrict__ out,
               int n_edges)
{
    const int tid  = threadIdx.x;
    const int wid  = tid >> 5;
    const int lane = tid & 31;
    const int g    = lane >> 2;
    const int t    = lane & 3;
    const int mw   = wid >> 2;      // m-group (0..1): mtiles mw*4..+3
    const int nw   = wid & 3;       // n-group (0..3): ntiles nw*4..+3
    const uint32_t sbase = smem_u32(smem);

    int* sxi = (int*)(smem + OFF_SXI);
    int* syi = (int*)(smem + OFF_SYI);
    float* sb1  = (float*)(smem + OFF_SB1);
    float* sw2  = (float*)(smem + OFF_SW2);
    float* sred = (float*)(smem + OFF_SRED);

    const int idx64 = g_idx_is64;
    const long long* xi64 = (const long long*)x_idx_raw;
    const long long* yi64 = (const long long*)y_idx_raw;
    const int*       xi32 = (const int*)x_idx_raw;
    const int*       yi32 = (const int*)y_idx_raw;

    // ---- one-time: W1 -> fp16 B fragment table ----
    for (int i = tid; i < 16 * 16 * 32; i += THREADS) {
        int nt = i >> 9, ks = (i >> 5) & 15, l = i & 31;
        int gg = l >> 2, tt = l & 3;
        int k0 = ks * 16 + 2 * tt, n = nt * 8 + gg;
        uint32_t b0 = f2h2(W1[k0 * NHID + n],       W1[(k0 + 1) * NHID + n]);
        uint32_t b1 = f2h2(W1[(k0 + 8) * NHID + n], W1[(k0 + 9) * NHID + n]);
        *(uint2*)(smem + OFF_BFRAG + (size_t)i * 8) = make_uint2(b0, b1);
    }
    for (int i = tid; i < NHID; i += THREADS) { sb1[i] = bias1[i]; sw2[i] = W2[i]; }
    const float b2 = bias2[0];

    __syncthreads();

    // gather geometry: thread covers edges ge+16r (r=0..7), float4 slot gq
    const int ge = tid >> 4;        // 0..15
    const int gq = tid & 15;        // float4 index within 64-float chunk

    // ldmatrix per-lane address component: row (lane&15), k-half (lane>>4)
    const uint32_t lm_off = (uint32_t)(lane & 15) * AROW + (uint32_t)(lane >> 4) * 16;

    const int ntiles = (n_edges + TILE_M - 1) / TILE_M;
    for (int tile = blockIdx.x; tile < ntiles; tile += GRID) {
        const int ebase = tile * TILE_M;

        for (int i = tid; i < TILE_M; i += THREADS) {
            int e = ebase + i; if (e >= n_edges) e = n_edges - 1;
            sxi[i] = idx64 ? (int)xi64[e] : xi32[e];
            syi[i] = idx64 ? (int)yi64[e] : yi32[e];
        }
        __syncthreads();

        float4 pf[4];
        // prefetch half h (edges ge + (4h+r)*16, r=0..3) of chunk c
        auto prefetch = [&](int c, int h) {
            const int* idxarr = (c < 2) ? sxi : syi;
            const int kbase = (c & 1) * 64;
            #pragma unroll
            for (int r = 0; r < 4; ++r) {
                int e = ge + (h * 4 + r) * 16;
                pf[r] = *(const float4*)(inputs + (size_t)idxarr[e] * NHID + kbase + gq * 4);
            }
        };
        // convert + store row-major fp16 (one STS.64 per float4)
        auto sts_half = [&](int c, int h) {
            const uint32_t abuf = sbase + ((c & 1) ? OFF_AF1 : OFF_AF0);
            #pragma unroll
            for (int r = 0; r < 4; ++r) {
                int e = ge + (h * 4 + r) * 16;
                sts64(abuf + (uint32_t)e * AROW + (uint32_t)gq * 8,
                      f2h2(pf[r].x, pf[r].y), f2h2(pf[r].z, pf[r].w));
            }
        };

        prefetch(0, 0); sts_half(0, 0);
        prefetch(0, 1); sts_half(0, 1);
        __syncthreads();

        float acc[4][4][4];
        #pragma unroll
        for (int mt = 0; mt < 4; ++mt)
            #pragma unroll
            for (int nt = 0; nt < 4; ++nt)
                #pragma unroll
                for (int r = 0; r < 4; ++r) acc[mt][nt][r] = 0.0f;

        for (int c = 0; c < NCHUNKS; ++c) {
            const uint32_t abuf = sbase + ((c & 1) ? OFF_AF1 : OFF_AF0);

            if (c < NCHUNKS - 1) prefetch(c + 1, 0);

            #pragma unroll
            for (int ks = 0; ks < 4; ++ks) {
                if (ks == 2 && c < NCHUNKS - 1) {   // mid-loop: commit half0, fetch half1
                    sts_half(c + 1, 0);
                    prefetch(c + 1, 1);
                }
                const int gks = c * 4 + ks;
                uint2 bf[4];
                #pragma unroll
                for (int nt = 0; nt < 4; ++nt)
                    bf[nt] = *(const uint2*)(smem + OFF_BFRAG +
                              (size_t)(((nw * 4 + nt) * 16 + gks) * 32 + lane) * 8);
                #pragma unroll
                for (int mt = 0; mt < 4; ++mt) {
                    // A tile rows (mw*4+mt)*16 .. +15, k bytes ks*32 .. +31
                    uint32_t a0, a1, a2, a3;
                    ldsm4(a0, a1, a2, a3,
                          abuf + (uint32_t)((mw * 4 + mt) * 16) * AROW
                               + (uint32_t)ks * 32 + lm_off);
                    #pragma unroll
                    for (int nt = 0; nt < 4; ++nt)
                        mma_f16(acc[mt][nt][0], acc[mt][nt][1],
                                acc[mt][nt][2], acc[mt][nt][3],
                                a0, a1, a2, a3, bf[nt].x, bf[nt].y);
                }
            }

            if (c < NCHUNKS - 1) {
                sts_half(c + 1, 1);
                __syncthreads();
            }
        }

        // ---- epilogue: relu + W2 dot (consts from smem), reduce lanes/groups ----
        #pragma unroll
        for (int mt = 0; mt < 4; ++mt) {
            #pragma unroll
            for (int h = 0; h < 2; ++h) {
                float s = 0.0f;
                #pragma unroll
                for (int nt = 0; nt < 4; ++nt) {
                    int col = (nw * 4 + nt) * 8 + t * 2;
                    float ca = acc[mt][nt][h * 2];
                    float cb = acc[mt][nt][h * 2 + 1];
                    s += fmaxf(ca + sb1[col],     0.0f) * sw2[col];
                    s += fmaxf(cb + sb1[col + 1], 0.0f) * sw2[col + 1];
                }
                s += __shfl_xor_sync(0xffffffffu, s, 1);
                s += __shfl_xor_sync(0xffffffffu, s, 2);
                if (t == 0) {
                    int row = (mw * 4 + mt) * 16 + g + h * 8;
                    sred[row * 4 + nw] = s;
                }
            }
        }
        __syncthreads();

        if (tid < TILE_M) {
            float4 v = *(const float4*)(sred + tid * 4);
            float sum = (v.x + v.y) + (v.z + v.w) + b2;
            int e = ebase + tid;
            if (e < n_edges)
                out[e] = 1.0f / (1.0f + __expf(-sum));
        }
        __syncthreads();
    }
}

// ---------------- launch ----------------
extern "C" void kernel_launch(void* const* d_in, const int* in_sizes, int n_in,
                              void* d_out, int out_size)
{
    const float* inputs = (const float*)d_in[0];
    const void*  x_idx  = d_in[1];
    const void*  y_idx  = d_in[2];
    const float* W1     = (const float*)d_in[3];
    const float* bias1  = (const float*)d_in[4];
    const float* W2     = (const float*)d_in[5];
    const float* bias2  = (const float*)d_in[6];
    float* out = (float*)d_out;

    const int n_edges = in_sizes[1];
    const int n_nodes = in_sizes[0] / NHID;

    detect_idx_width<<<1, 1>>>((const long long*)x_idx, n_nodes);

    cudaFuncSetAttribute(mlp_decoder_h5,
                         cudaFuncAttributeMaxDynamicSharedMemorySize, SMEM_TOTAL);
    mlp_decoder_h5<<<GRID, THREADS, SMEM_TOTAL>>>(
        inputs, x_idx, y_idx, W1, bias1, W2, bias2, out, n_edges);
}

// round 11
// speedup vs baseline: 1.4002x; 1.0051x over previous
#include <cuda_runtime.h>
#include <cuda_fp16.h>
#include <cstdint>

#define NHID     128
#define KDIM     256
#define TILE_M   128
#define THREADS  256
#define NCTAS    2
#define GRID     (152 * NCTAS)
#define NCHUNKS  4       // 64-wide k chunks
#define AROW     144     // bytes per staged edge row (64 fp16 = 128B + 16B pad)

// ---------------- smem layout (bytes, per CTA) ----------------
#define OFF_BFRAG  0
#define OFF_AF0    65536
#define OFF_AF1    83968
#define OFF_SXI    102400
#define OFF_SYI    102912
#define OFF_SB1    103424
#define OFF_SW2    103936
#define OFF_SRED   104448
#define SMEM_TOTAL 106496

// ---------------- PTX helpers ----------------
__device__ __forceinline__ uint32_t smem_u32(const void* p) {
    uint32_t a;
    asm("{ .reg .u64 t; cvta.to.shared.u64 t, %1; cvt.u32.u64 %0, t; }" : "=r"(a) : "l"(p));
    return a;
}
__device__ __forceinline__ uint32_t f2h2(float lo, float hi) {
    uint32_t v;
    asm("cvt.rn.f16x2.f32 %0, %1, %2;" : "=r"(v) : "f"(hi), "f"(lo));
    return v;
}
__device__ __forceinline__ void sts64(uint32_t addr, uint32_t v0, uint32_t v1) {
    asm volatile("st.shared.v2.b32 [%0], {%1, %2};" :: "r"(addr), "r"(v0), "r"(v1) : "memory");
}
__device__ __forceinline__ void ldsm4(uint32_t& r0, uint32_t& r1, uint32_t& r2, uint32_t& r3,
                                      uint32_t addr) {
    asm volatile("ldmatrix.sync.aligned.m8n8.x4.shared.b16 {%0,%1,%2,%3}, [%4];"
                 : "=r"(r0), "=r"(r1), "=r"(r2), "=r"(r3) : "r"(addr));
}
__device__ __forceinline__ void mma_f16(float& c0, float& c1, float& c2, float& c3,
                                        uint32_t a0, uint32_t a1, uint32_t a2, uint32_t a3,
                                        uint32_t b0, uint32_t b1) {
    asm volatile("mma.sync.aligned.m16n8k16.row.col.f32.f16.f16.f32 "
                 "{%0,%1,%2,%3}, {%4,%5,%6,%7}, {%8,%9}, {%0,%1,%2,%3};"
                 : "+f"(c0), "+f"(c1), "+f"(c2), "+f"(c3)
                 : "r"(a0), "r"(a1), "r"(a2), "r"(a3), "r"(b0), "r"(b1));
}
// half-CTA barrier: id = mw+1, 128 threads
__device__ __forceinline__ void bar_half(int id) {
    asm volatile("bar.sync %0, %1;" :: "r"(id), "r"(128) : "memory");
}

// ---------------- index width autodetect ----------------
__device__ int g_idx_is64;
__global__ void detect_idx_width(const long long* xi, int n_nodes) {
    int is64 = 1;
    for (int i = 0; i < 16; ++i) {
        long long v = xi[i];
        if (v < 0 || v >= (long long)n_nodes) { is64 = 0; break; }
    }
    g_idx_is64 = is64;
}

// ---------------- main kernel ----------------
extern __shared__ char smem[];

__global__ void __launch_bounds__(THREADS, NCTAS)
mlp_decoder_h6(const float* __restrict__ inputs,
               const void*  __restrict__ x_idx_raw,
               const void*  __restrict__ y_idx_raw,
               const float* __restrict__ W1,
               const float* __restrict__ bias1,
               const float* __restrict__ W2,
               const float* __restrict__ bias2,
               float* __restrict__ out,
               int n_edges)
{
    const int tid  = threadIdx.x;
    const int wid  = tid >> 5;
    const int lane = tid & 31;
    const int g    = lane >> 2;
    const int t    = lane & 3;
    const int mw   = tid >> 7;       // half-CTA / m-group (0..1)
    const int nw   = wid & 3;        // n-group (0..3)
    const int gtid = tid & 127;      // id within half
    const int barid = mw + 1;
    const uint32_t sbase = smem_u32(smem);

    int* sxi = (int*)(smem + OFF_SXI);
    int* syi = (int*)(smem + OFF_SYI);
    float* sb1  = (float*)(smem + OFF_SB1);
    float* sw2  = (float*)(smem + OFF_SW2);
    float* sred = (float*)(smem + OFF_SRED);

    const int idx64 = g_idx_is64;
    const long long* xi64 = (const long long*)x_idx_raw;
    const long long* yi64 = (const long long*)y_idx_raw;
    const int*       xi32 = (const int*)x_idx_raw;
    const int*       yi32 = (const int*)y_idx_raw;

    // ---- one-time: W1 -> fp16 B fragment table (whole CTA) ----
    for (int i = tid; i < 16 * 16 * 32; i += THREADS) {
        int nt = i >> 9, ks = (i >> 5) & 15, l = i & 31;
        int gg = l >> 2, tt = l & 3;
        int k0 = ks * 16 + 2 * tt, n = nt * 8 + gg;
        uint32_t b0 = f2h2(W1[k0 * NHID + n],       W1[(k0 + 1) * NHID + n]);
        uint32_t b1 = f2h2(W1[(k0 + 8) * NHID + n], W1[(k0 + 9) * NHID + n]);
        *(uint2*)(smem + OFF_BFRAG + (size_t)i * 8) = make_uint2(b0, b1);
    }
    for (int i = tid; i < NHID; i += THREADS) { sb1[i] = bias1[i]; sw2[i] = W2[i]; }
    const float b2 = bias2[0];

    __syncthreads();   // only full-CTA barrier; halves run independently below

    // gather geometry within the half: 64 owned edges
    const int ge_l = gtid >> 4;     // 0..7
    const int gq   = gtid & 15;     // float4 slot within 64-float chunk

    const uint32_t lm_off = (uint32_t)(lane & 15) * AROW + (uint32_t)(lane >> 4) * 16;

    const int ntiles = (n_edges + TILE_M - 1) / TILE_M;
    for (int tile = blockIdx.x; tile < ntiles; tile += GRID) {
        const int ebase = tile * TILE_M;

        // stage this half's 64 indices (x by gtid<64, y by gtid>=64)
        {
            int j = mw * 64 + (gtid & 63);
            int e = ebase + j; if (e >= n_edges) e = n_edges - 1;
            if (gtid < 64) sxi[j] = idx64 ? (int)xi64[e] : xi32[e];
            else           syi[j] = idx64 ? (int)yi64[e] : yi32[e];
        }
        bar_half(barid);

        float4 pf[4];
        // prefetch half-of-chunk h (32 owned edges) of chunk c
        auto prefetch = [&](int c, int h) {
            const int* idxarr = (c < 2) ? sxi : syi;
            const int kbase = (c & 1) * 64;
            #pragma unroll
            for (int r = 0; r < 4; ++r) {
                int e = mw * 64 + h * 32 + r * 8 + ge_l;
                pf[r] = *(const float4*)(inputs + (size_t)idxarr[e] * NHID + kbase + gq * 4);
            }
        };
        auto sts_half = [&](int c, int h) {
            const uint32_t abuf = sbase + ((c & 1) ? OFF_AF1 : OFF_AF0);
            #pragma unroll
            for (int r = 0; r < 4; ++r) {
                int e = mw * 64 + h * 32 + r * 8 + ge_l;
                sts64(abuf + (uint32_t)e * AROW + (uint32_t)gq * 8,
                      f2h2(pf[r].x, pf[r].y), f2h2(pf[r].z, pf[r].w));
            }
        };

        prefetch(0, 0); sts_half(0, 0);
        prefetch(0, 1); sts_half(0, 1);
        bar_half(barid);

        float acc[4][4][4];
        #pragma unroll
        for (int mt = 0; mt < 4; ++mt)
            #pragma unroll
            for (int nt = 0; nt < 4; ++nt)
                #pragma unroll
                for (int r = 0; r < 4; ++r) acc[mt][nt][r] = 0.0f;

        for (int c = 0; c < NCHUNKS; ++c) {
            const uint32_t abuf = sbase + ((c & 1) ? OFF_AF1 : OFF_AF0);

            if (c < NCHUNKS - 1) prefetch(c + 1, 0);

            #pragma unroll
            for (int ks = 0; ks < 4; ++ks) {
                if (ks == 1 && c < NCHUNKS - 1) {   // early: commit half0, launch half1
                    sts_half(c + 1, 0);
                    prefetch(c + 1, 1);
                }
                if (ks == 3 && c < NCHUNKS - 1) {   // commit half1 before barrier
                    sts_half(c + 1, 1);
                }
                const int gks = c * 4 + ks;
                uint2 bf[4];
                #pragma unroll
                for (int nt = 0; nt < 4; ++nt)
                    bf[nt] = *(const uint2*)(smem + OFF_BFRAG +
                              (size_t)(((nw * 4 + nt) * 16 + gks) * 32 + lane) * 8);
                #pragma unroll
                for (int mt = 0; mt < 4; ++mt) {
                    uint32_t a0, a1, a2, a3;
                    ldsm4(a0, a1, a2, a3,
                          abuf + (uint32_t)((mw * 4 + mt) * 16) * AROW
                               + (uint32_t)ks * 32 + lm_off);
                    #pragma unroll
                    for (int nt = 0; nt < 4; ++nt)
                        mma_f16(acc[mt][nt][0], acc[mt][nt][1],
                                acc[mt][nt][2], acc[mt][nt][3],
                                a0, a1, a2, a3, bf[nt].x, bf[nt].y);
                }
            }

            if (c < NCHUNKS - 1) bar_half(barid);
        }

        // ---- epilogue (per half): relu + W2 dot, reduce lanes/groups ----
        #pragma unroll
        for (int mt = 0; mt < 4; ++mt) {
            #pragma unroll
            for (int h = 0; h < 2; ++h) {
                float s = 0.0f;
                #pragma unroll
                for (int nt = 0; nt < 4; ++nt) {
                    int col = (nw * 4 + nt) * 8 + t * 2;
                    float ca = acc[mt][nt][h * 2];
                    float cb = acc[mt][nt][h * 2 + 1];
                    s += fmaxf(ca + sb1[col],     0.0f) * sw2[col];
                    s += fmaxf(cb + sb1[col + 1], 0.0f) * sw2[col + 1];
                }
                s += __shfl_xor_sync(0xffffffffu, s, 1);
                s += __shfl_xor_sync(0xffffffffu, s, 2);
                if (t == 0) {
                    int row = (mw * 4 + mt) * 16 + g + h * 8;
                    sred[row * 4 + nw] = s;
                }
            }
        }
        bar_half(barid);

        if (gtid < 64) {
            int row = mw * 64 + gtid;
            float4 v = *(const float4*)(sred + row * 4);
            float sum = (v.x + v.y) + (v.z + v.w) + b2;
            int e = ebase + row;
            if (e < n_edges)
                out[e] = 1.0f / (1.0f + __expf(-sum));
        }
        bar_half(barid);   // sred/sxi consumed before next tile overwrites
    }
}

// ---------------- launch ----------------
extern "C" void kernel_launch(void* const* d_in, const int* in_sizes, int n_in,
                              void* d_out, int out_size)
{
    const float* inputs = (const float*)d_in[0];
    const void*  x_idx  = d_in[1];
    const void*  y_idx  = d_in[2];
    const float* W1     = (const float*)d_in[3];
    const float* bias1  = (const float*)d_in[4];
    const float* W2     = (const float*)d_in[5];
    const float* bias2  = (const float*)d_in[6];
    float* out = (float*)d_out;

    const int n_edges = in_sizes[1];
    const int n_nodes = in_sizes[0] / NHID;

    detect_idx_width<<<1, 1>>>((const long long*)x_idx, n_nodes);

    cudaFuncSetAttribute(mlp_decoder_h6,
                         cudaFuncAttributeMaxDynamicSharedMemorySize, SMEM_TOTAL);
    mlp_decoder_h6<<<GRID, THREADS, SMEM_TOTAL>>>(
        inputs, x_idx, y_idx, W1, bias1, W2, bias2, out, n_edges);
}